// round 4
// baseline (speedup 1.0000x reference)
#include <cuda_runtime.h>
#include <cstdint>

// C = B @ A^T ; A:(8192,64) B:(8192,64) C_faulty:(8192,8192)
// Output = C_faulty with sparse (+100) faults replaced by recomputed C_true.
// Detection unit: one warp-slab = 8 rows x 128 cols. 65536 slabs total.

#define M_DIM 8192
#define N_DIM 8192
#define D_DIM 64

#define SLAB_R 8                       // slab rows (one warp)
#define TILE_C 128                     // slab cols
#define NS_R (M_DIM / SLAB_R)          // 1024 slab rows
#define NT_C (N_DIM / TILE_C)          // 64 col tiles
#define NUM_SLABS (NS_R * NT_C)        // 65536

#define THRESH 50.0f
#define MAX_FLAGS NUM_SLABS

#define GRID_MAIN 592                  // 4 CTAs/SM x 148 SMs (grid-stride safe)

// Scratch (allocation-free)
__device__ float d_BC8[NS_R * D_DIM];  // per-8-row B checksums (256KB)
__device__ float d_AC[NT_C * D_DIM];   // per-128-col A checksums (16KB)
__device__ int   d_flags[MAX_FLAGS];
__device__ int   d_count;

// ---------------------------------------------------------------------------
// Kernel 1: operand checksums + counter reset. grid = 256 + 64 = 320.
//  blocks [0,256):  block g -> B slabs 4g..4g+3 (t: d=t&63 col, q=t>>6 slab)
//  blocks [256,320): A col-tile checksums (128 rows, smem reduce)
// ---------------------------------------------------------------------------
__global__ void checksum_kernel(const float* __restrict__ A,
                                const float* __restrict__ B) {
    __shared__ float red[256];
    int g = blockIdx.x;
    int t = threadIdx.x;
    int d = t & 63;
    int q = t >> 6;

    if (g == 0 && t == 0) d_count = 0;

    if (g < 256) {
        int slab = g * 4 + q;
        const float* p = B + (size_t)slab * SLAB_R * D_DIM + d;
        float s = 0.0f;
        #pragma unroll
        for (int r = 0; r < SLAB_R; r++) s += p[r * D_DIM];
        d_BC8[slab * D_DIM + d] = s;
    } else {
        int ga = g - 256;
        const float* p = A + ((size_t)ga * TILE_C + q * 32) * D_DIM + d;
        float s = 0.0f;
        #pragma unroll
        for (int r = 0; r < 32; r++) s += p[r * D_DIM];
        red[t] = s;
        __syncthreads();
        if (q == 0)
            d_AC[ga * D_DIM + d] = red[d] + red[d + 64] + red[d + 128] + red[d + 192];
    }
}

// ---------------------------------------------------------------------------
// Kernel 2: warp-persistent fused copy + detection. NO __syncthreads.
// Each warp grid-strides over 8x128 slabs: 8 front-batched LDG.128 per lane,
// fold expected checksum (2 FMA/lane from BC8/AC, L2-resident), 8 STG.128,
// warp shuffle reduce, lane0 flags via atomic.
// ---------------------------------------------------------------------------
__global__ void __launch_bounds__(256, 4)
main_pass_kernel(const float* __restrict__ C, float* __restrict__ out) {
    const int lane   = threadIdx.x & 31;
    const int gwarp  = blockIdx.x * 8 + (threadIdx.x >> 5);
    const int nwarps = gridDim.x * 8;
    const int stride4 = N_DIM / 4;     // float4 row stride

    for (int idx = gwarp; idx < NUM_SLABS; idx += nwarps) {
        int sr = idx >> 6;             // slab row 0..1023
        int tj = idx & 63;             // col tile 0..63

        const size_t base = (size_t)sr * SLAB_R * N_DIM + (size_t)tj * TILE_C + lane * 4;
        const float4* __restrict__ src = (const float4*)(C + base);
        float4*       __restrict__ dst = (float4*)(out + base);

        float4 v[8];
        #pragma unroll
        for (int i = 0; i < 8; i++) v[i] = __ldcs(src + i * stride4);

        // expected checksum partial: 2 of 64 dims per lane (L2-resident tables)
        const float* bc = d_BC8 + sr * D_DIM + lane;
        const float* ac = d_AC  + tj * D_DIM + lane;
        float s = -(bc[0] * ac[0] + bc[32] * ac[32]);

        #pragma unroll
        for (int i = 0; i < 8; i++) s += (v[i].x + v[i].y) + (v[i].z + v[i].w);

        #pragma unroll
        for (int i = 0; i < 8; i++) __stcs(dst + i * stride4, v[i]);

        // warp reduce -> slab residual
        #pragma unroll
        for (int o = 16; o > 0; o >>= 1) s += __shfl_down_sync(0xFFFFFFFFu, s, o);

        if (lane == 0 && fabsf(s) > THRESH) {
            int slot = atomicAdd(&d_count, 1);
            if (slot < MAX_FLAGS) d_flags[slot] = idx;
        }
    }
}

// ---------------------------------------------------------------------------
// Kernel 3: repair flagged 8x128 slabs. 1024 CTAs x 128 threads, round-robin.
// Per slab: B rows (8x64, 2KB) in smem; thread owns output column (A row in
// 16 float4 regs), 8 dot-64 products with 4-way split accumulators.
// ---------------------------------------------------------------------------
__global__ void __launch_bounds__(128)
repair_kernel(const float* __restrict__ A, const float* __restrict__ B,
              const float* __restrict__ Cf, float* __restrict__ out) {
    __shared__ float Bs[SLAB_R * D_DIM];  // 2KB
    int nf = d_count;
    if (nf > MAX_FLAGS) nf = MAX_FLAGS;

    for (int f = blockIdx.x; f < nf; f += gridDim.x) {
        int sid = d_flags[f];
        int sr = sid >> 6;
        int tj = sid & 63;
        size_t r0 = (size_t)sr * SLAB_R;
        size_t c0 = (size_t)tj * TILE_C;

        __syncthreads();  // protect Bs reuse across loop iterations
        for (int i = threadIdx.x; i < SLAB_R * D_DIM; i += blockDim.x)
            Bs[i] = B[r0 * D_DIM + i];
        __syncthreads();

        const float4* Arow = (const float4*)(A + (c0 + threadIdx.x) * (size_t)D_DIM);
        float4 a[16];
        #pragma unroll
        for (int k = 0; k < 16; k++) a[k] = __ldg(&Arow[k]);

        #pragma unroll
        for (int r = 0; r < SLAB_R; r++) {
            const float4* Brow = (const float4*)(Bs + r * D_DIM);
            float a0 = 0.f, a1 = 0.f, a2 = 0.f, a3 = 0.f;
            #pragma unroll
            for (int k = 0; k < 16; k += 4) {
                float4 b0 = Brow[k], b1 = Brow[k+1], b2 = Brow[k+2], b3 = Brow[k+3];
                a0 += a[k].x   * b0.x + a[k].y   * b0.y + a[k].z   * b0.z + a[k].w   * b0.w;
                a1 += a[k+1].x * b1.x + a[k+1].y * b1.y + a[k+1].z * b1.z + a[k+1].w * b1.w;
                a2 += a[k+2].x * b2.x + a[k+2].y * b2.y + a[k+2].z * b2.z + a[k+2].w * b2.w;
                a3 += a[k+3].x * b3.x + a[k+3].y * b3.y + a[k+3].z * b3.z + a[k+3].w * b3.w;
            }
            float acc = (a0 + a1) + (a2 + a3);
            size_t off = (r0 + r) * (size_t)N_DIM + c0 + threadIdx.x;
            float cf = __ldg(&Cf[off]);
            if (fabsf(cf - acc) > THRESH) out[off] = acc;
        }
    }
}

// ---------------------------------------------------------------------------
extern "C" void kernel_launch(void* const* d_in, const int* in_sizes, int n_in,
                              void* d_out, int out_size) {
    const float* A  = (const float*)d_in[0];
    const float* B  = (const float*)d_in[1];
    const float* Cf = (const float*)d_in[2];
    float* out = (float*)d_out;

    checksum_kernel<<<320, 256>>>(A, B);
    main_pass_kernel<<<GRID_MAIN, 256>>>(Cf, out);
    repair_kernel<<<1024, 128>>>(A, B, Cf, out);
}